// round 2
// baseline (speedup 1.0000x reference)
#include <cuda_runtime.h>

// DigitCaps dynamic routing, GB300 sm_103a — full fp32, recompute-fused.
// B=64, I=4096, Din=8, N=10, D=16, 3 routing iterations.
//
// Per iteration: one k_pass kernel (fused u-recompute + agreement + logit
// update + softmax + weighted partial sums), then k_finish (256-way partial
// reduction + elementwise squash). No u_hat materialization, no atomics.

#define B_ 64
#define I_ 4096
#define P_ 8
#define N_ 10
#define D_ 16
#define ND_ 160
#define CHUNK 16                 // input capsules per block
#define NBLK (I_ / CHUNK)        // 256 blocks
#define THREADS 640              // 64 b-lanes x 10 n-warps
#define PART_STRIDE (B_ * ND_)   // 10240

// Scratch (static device globals; no allocation)
__device__ float g_part[(size_t)NBLK * PART_STRIDE];  // per-block partial sums, 10.5MB
__device__ float g_blog[(size_t)I_ * B_ * N_];        // routing logits [i][b][n], 10.5MB
__device__ float g_v[B_ * ND_];                       // squashed v

static __device__ __forceinline__ unsigned long long pack2(float a, float b) {
    unsigned long long r;
    asm("mov.b64 %0, {%1,%2};" : "=l"(r) : "f"(a), "f"(b));
    return r;
}
static __device__ __forceinline__ float2 unpack2(unsigned long long v) {
    float2 r;
    asm("mov.b64 {%0,%1}, %2;" : "=f"(r.x), "=f"(r.y) : "l"(v));
    return r;
}
static __device__ __forceinline__ unsigned long long ffma2(
    unsigned long long a, unsigned long long b, unsigned long long c) {
    unsigned long long d;
    asm("fma.rn.f32x2 %0, %1, %2, %3;" : "=l"(d) : "l"(a), "l"(b), "l"(c));
    return d;
}
static __device__ __forceinline__ unsigned long long fadd2(
    unsigned long long a, unsigned long long b) {
    unsigned long long d;
    asm("add.rn.f32x2 %0, %1, %2;" : "=l"(d) : "l"(a), "l"(b));
    return d;
}

// One routing iteration, fused.
// Thread (b, n): for each of the block's 16 i's, recompute the t-tile
// u[b,i,n,0:16] in registers from smem-staged x and W, use it for BOTH the
// agreement (PASS>0) and the c-weighted accumulation.
template <int PASS>
__global__ __launch_bounds__(THREADS) void k_pass(const float* __restrict__ X,
                                                  const float* __restrict__ W) {
    __shared__ __align__(16) float s_x[CHUNK * P_ * B_];   // [il][p][b], 32KB
    __shared__ __align__(16) float s_w[2][N_ * P_ * D_];   // double-buffered W[i], 10KB
    __shared__ float s_a[2][B_ * 11];                      // bn logits, padded stride 11

    int tid = threadIdx.x;
    int n = tid >> 6;        // warp-uniform
    int b = tid & 63;
    int i0 = blockIdx.x * CHUNK;

    // Stage x for the whole chunk (coalesced: 128 consecutive floats per batch)
    for (int idx = tid; idx < CHUNK * P_ * B_; idx += THREADS) {
        int bb = idx >> 7;       // batch
        int r = idx & 127;       // il*8 + p
        s_x[r * B_ + bb] = X[(size_t)bb * (I_ * P_) + i0 * P_ + r];
    }
    // Stage W for il=0 (1280 floats, 2 per thread)
    {
        float2 w0 = *(const float2*)(W + (size_t)i0 * 1280 + tid * 2);
        *(float2*)&s_w[0][tid * 2] = w0;
    }
    // v for this (b, n) in registers (8 f32x2 pairs)
    unsigned long long v2[8];
    if (PASS > 0) {
        const float4* vp = (const float4*)(g_v + b * ND_ + n * D_);
#pragma unroll
        for (int j = 0; j < 4; j++) {
            float4 f = vp[j];
            v2[2 * j] = pack2(f.x, f.y);
            v2[2 * j + 1] = pack2(f.z, f.w);
        }
    }
    __syncthreads();

    unsigned long long sacc[8];
#pragma unroll
    for (int j = 0; j < 8; j++) sacc[j] = 0ULL;

#pragma unroll 2
    for (int il = 0; il < CHUNK; il++) {
        int buf = il & 1;

        // Prefetches (consumed after ~500 cyc of FMA work below)
        float2 wpf = make_float2(0.f, 0.f);
        if (il + 1 < CHUNK)
            wpf = *(const float2*)(W + (size_t)(i0 + il + 1) * 1280 + tid * 2);
        float gbv = 0.f;
        if (PASS == 2)
            gbv = g_blog[(size_t)(i0 + il) * (B_ * N_) + b * N_ + n];

        // Phase A: t[16] = sum_p x[b,i,p] * W[i,n,p,:]   (8 f32x2 accumulators)
        unsigned long long t2[8];
#pragma unroll
        for (int j = 0; j < 8; j++) t2[j] = 0ULL;
        const float* wbase = &s_w[buf][n * (P_ * D_)];
#pragma unroll
        for (int p = 0; p < P_; p++) {
            float xv = s_x[(il * P_ + p) * B_ + b];        // conflict-free (b = lane)
            unsigned long long xp = pack2(xv, xv);
            const ulonglong2* wv = (const ulonglong2*)(wbase + p * D_);  // uniform bcast
#pragma unroll
            for (int q = 0; q < 4; q++) {
                ulonglong2 w = wv[q];
                t2[2 * q] = ffma2(xp, w.x, t2[2 * q]);
                t2[2 * q + 1] = ffma2(xp, w.y, t2[2 * q + 1]);
            }
        }

        // Agreement + logit update (per-(b,i) local)
        if (PASS > 0) {
            unsigned long long aa = 0ULL;
#pragma unroll
            for (int j = 0; j < 8; j++) aa = ffma2(t2[j], v2[j], aa);
            float2 af = unpack2(aa);
            float bn = af.x + af.y + (PASS == 2 ? gbv : 0.f);
            g_blog[(size_t)(i0 + il) * (B_ * N_) + b * N_ + n] = bn;
            s_a[buf][b * 11 + n] = bn;
        }
        // Stage next i's W into the other buffer (safe: readers use s_w[buf])
        if (il + 1 < CHUNK)
            *(float2*)&s_w[1 - buf][tid * 2] = wpf;

        __syncthreads();

        if (PASS > 0) {
            // softmax over n (each of the 10 n-threads per b redundantly)
            float bnv[10];
#pragma unroll
            for (int k = 0; k < 10; k++) bnv[k] = s_a[buf][b * 11 + k];
            float m = bnv[0];
#pragma unroll
            for (int k = 1; k < 10; k++) m = fmaxf(m, bnv[k]);
            float Z = 0.f, eo = 0.f;
#pragma unroll
            for (int k = 0; k < 10; k++) {
                float e = __expf(bnv[k] - m);
                Z += e;
                if (k == n) eo = e;
            }
            float c = __fdividef(eo, Z);
            unsigned long long cp = pack2(c, c);
#pragma unroll
            for (int j = 0; j < 8; j++) sacc[j] = ffma2(cp, t2[j], sacc[j]);
        } else {
            // c uniform = 1/10: accumulate raw, scale at the end
#pragma unroll
            for (int j = 0; j < 8; j++) sacc[j] = fadd2(sacc[j], t2[j]);
        }
    }

    // Per-block partials (distinct addresses; no atomics)
    float4* po = (float4*)(g_part + (size_t)blockIdx.x * PART_STRIDE + b * ND_ + n * D_);
#pragma unroll
    for (int q = 0; q < 4; q++) {
        float2 f0 = unpack2(sacc[2 * q]);
        float2 f1 = unpack2(sacc[2 * q + 1]);
        if (PASS == 0) {
            f0.x *= 0.1f; f0.y *= 0.1f; f1.x *= 0.1f; f1.y *= 0.1f;
        }
        po[q] = make_float4(f0.x, f0.y, f1.x, f1.y);
    }
}

// 256-way partial reduction + elementwise squash (fixed order -> deterministic)
template <bool FINAL>
__global__ __launch_bounds__(256) void k_finish(float* __restrict__ dout) {
    int idx = blockIdx.x * 256 + threadIdx.x;   // exactly 10240 threads
    const float* p = g_part + idx;
    float a0 = 0.f, a1 = 0.f, a2 = 0.f, a3 = 0.f;
    float a4 = 0.f, a5 = 0.f, a6 = 0.f, a7 = 0.f;
#pragma unroll 4
    for (int k = 0; k < NBLK; k += 8) {
        a0 += p[(size_t)(k + 0) * PART_STRIDE];
        a1 += p[(size_t)(k + 1) * PART_STRIDE];
        a2 += p[(size_t)(k + 2) * PART_STRIDE];
        a3 += p[(size_t)(k + 3) * PART_STRIDE];
        a4 += p[(size_t)(k + 4) * PART_STRIDE];
        a5 += p[(size_t)(k + 5) * PART_STRIDE];
        a6 += p[(size_t)(k + 6) * PART_STRIDE];
        a7 += p[(size_t)(k + 7) * PART_STRIDE];
    }
    float s = ((a0 + a1) + (a2 + a3)) + ((a4 + a5) + (a6 + a7));
    float sq = s * s;
    float scale = sq / ((1.f + sq) * sqrtf(sq + 1e-7f));
    float v = scale * s;
    if (FINAL) dout[idx] = v;
    else       g_v[idx] = v;
}

extern "C" void kernel_launch(void* const* d_in, const int* in_sizes, int n_in,
                              void* d_out, int out_size) {
    const float* X = (const float*)d_in[0];
    const float* W = (const float*)d_in[1];
    if (n_in >= 2 && in_sizes[0] != B_ * I_ * P_) {  // robustness: identify by size
        const float* tmp = X; X = W; W = tmp;
    }

    k_pass<0><<<NBLK, THREADS>>>(X, W);
    k_finish<false><<<40, 256>>>(nullptr);
    k_pass<1><<<NBLK, THREADS>>>(X, W);
    k_finish<false><<<40, 256>>>(nullptr);
    k_pass<2><<<NBLK, THREADS>>>(X, W);
    k_finish<true><<<40, 256>>>((float*)d_out);
}

// round 3
// speedup vs baseline: 1.3995x; 1.3995x over previous
#include <cuda_runtime.h>

// DigitCaps dynamic routing, GB300 sm_103a — full fp32, recompute-fused, R3.
// B=64, I=4096, Din=8, N=10, D=16, 3 routing iterations.
//
// R3 changes vs R2 (184us):
//  - CHUNK 16->32: grid 128 = one wave at 1 block/SM (was 1.73 waves)
//  - softmax: ONE __expf per thread per i via two-stage smem exchange
//    (was 10 redundant MUFU/thread -> dominated SMSP issue)
//  - k_finish: 320-block two-level reduction (was grid=40, 14.5us)
//  - g_blog laid out [i][n*64+b] -> fully coalesced logit LDG/STG

#define B_ 64
#define I_ 4096
#define P_ 8
#define N_ 10
#define D_ 16
#define ND_ 160
#define CHUNK 32
#define NBLK (I_ / CHUNK)        // 128 blocks
#define THREADS 640              // 64 b-lanes x 10 n-warps
#define PART_STRIDE (B_ * ND_)   // 10240

// dynamic smem layout (floats)
#define SX_SZ (256 * 65)         // x staged [r=il*8+p][b], padded stride 65
#define SW_SZ (2 * 1280)         // double-buffered W[i][n][p][d]
#define SA_SZ (B_ * 11)          // logits bn, padded stride 11
#define SE_SZ (B_ * 11)          // exps
#define SMEM_FLOATS (SX_SZ + SW_SZ + SA_SZ + SE_SZ)
#define SMEM_BYTES (SMEM_FLOATS * 4)

__device__ float g_part[(size_t)NBLK * PART_STRIDE];  // per-block partials, 5.2MB
__device__ float g_blog[(size_t)I_ * B_ * N_];        // logits [i][n*64+b], 10.5MB
__device__ float g_v[B_ * ND_];                       // squashed v

static __device__ __forceinline__ unsigned long long pack2(float a, float b) {
    unsigned long long r;
    asm("mov.b64 %0, {%1,%2};" : "=l"(r) : "f"(a), "f"(b));
    return r;
}
static __device__ __forceinline__ float2 unpack2(unsigned long long v) {
    float2 r;
    asm("mov.b64 {%0,%1}, %2;" : "=f"(r.x), "=f"(r.y) : "l"(v));
    return r;
}
static __device__ __forceinline__ unsigned long long ffma2(
    unsigned long long a, unsigned long long b, unsigned long long c) {
    unsigned long long d;
    asm("fma.rn.f32x2 %0, %1, %2, %3;" : "=l"(d) : "l"(a), "l"(b), "l"(c));
    return d;
}
static __device__ __forceinline__ unsigned long long fadd2(
    unsigned long long a, unsigned long long b) {
    unsigned long long d;
    asm("add.rn.f32x2 %0, %1, %2;" : "=l"(d) : "l"(a), "l"(b));
    return d;
}

template <int PASS>
__global__ __launch_bounds__(THREADS, 1) void k_pass(const float* __restrict__ X,
                                                     const float* __restrict__ W) {
    extern __shared__ float smem[];
    float* s_x = smem;                 // [r][b] stride 65
    float* s_w = s_x + SX_SZ;
    float* s_a = s_w + SW_SZ;
    float* s_e = s_a + SA_SZ;

    int tid = threadIdx.x;
    int n = tid >> 6;        // warp-uniform
    int b = tid & 63;
    int i0 = blockIdx.x * CHUNK;

    // Stage x: 256 floats per batch, coalesced reads, conflict-free writes
    for (int idx = tid; idx < 256 * B_; idx += THREADS) {
        int bb = idx >> 8;
        int r = idx & 255;
        s_x[r * 65 + bb] = X[(size_t)bb * (I_ * P_) + i0 * P_ + r];
    }
    // Stage W for il=0
    {
        float2 w0 = *(const float2*)(W + (size_t)i0 * 1280 + tid * 2);
        *(float2*)&s_w[tid * 2] = w0;
    }
    // v for this (b, n) in registers
    unsigned long long v2[8];
    if (PASS > 0) {
        const float4* vp = (const float4*)(g_v + b * ND_ + n * D_);
#pragma unroll
        for (int j = 0; j < 4; j++) {
            float4 f = vp[j];
            v2[2 * j] = pack2(f.x, f.y);
            v2[2 * j + 1] = pack2(f.z, f.w);
        }
    }
    __syncthreads();

    unsigned long long sacc[8];
#pragma unroll
    for (int j = 0; j < 8; j++) sacc[j] = 0ULL;

    for (int il = 0; il < CHUNK; il++) {
        int buf = il & 1;

        // Prefetches
        float2 wpf;
        if (il + 1 < CHUNK)
            wpf = *(const float2*)(W + (size_t)(i0 + il + 1) * 1280 + tid * 2);
        float gbv = 0.f;
        if (PASS == 2)
            gbv = g_blog[(size_t)(i0 + il) * (B_ * N_) + tid];   // coalesced

        // u[b, i, n, 0:16] in 8 f32x2 accumulators
        unsigned long long t2[8];
#pragma unroll
        for (int j = 0; j < 8; j++) t2[j] = 0ULL;
        const float* wbase = &s_w[buf * 1280 + n * (P_ * D_)];
#pragma unroll
        for (int p = 0; p < P_; p++) {
            float xv = s_x[(il * P_ + p) * 65 + b];              // conflict-free
            unsigned long long xp = pack2(xv, xv);
            const ulonglong2* wv = (const ulonglong2*)(wbase + p * D_);  // bcast
#pragma unroll
            for (int q = 0; q < 4; q++) {
                ulonglong2 w = wv[q];
                t2[2 * q] = ffma2(xp, w.x, t2[2 * q]);
                t2[2 * q + 1] = ffma2(xp, w.y, t2[2 * q + 1]);
            }
        }

        if (PASS > 0) {
            // agreement + logit update
            unsigned long long aa = 0ULL;
#pragma unroll
            for (int j = 0; j < 8; j++) aa = ffma2(t2[j], v2[j], aa);
            float2 af = unpack2(aa);
            float bn = af.x + af.y + (PASS == 2 ? gbv : 0.f);
            g_blog[(size_t)(i0 + il) * (B_ * N_) + tid] = bn;    // coalesced
            s_a[b * 11 + n] = bn;                                // conflict-free
            if (il + 1 < CHUNK) *(float2*)&s_w[(1 - buf) * 1280 + tid * 2] = wpf;
            __syncthreads();   // sync1: bn visible, W(il+1) staged

            // softmax stage 1: ONE exp per thread
            float bnv[10];
#pragma unroll
            for (int k = 0; k < 10; k++) bnv[k] = s_a[b * 11 + k];
            float m = bnv[0];
#pragma unroll
            for (int k = 1; k < 10; k++) m = fmaxf(m, bnv[k]);
            float e = __expf(bnv[n] - m);
            s_e[b * 11 + n] = e;
            __syncthreads();   // sync2: exps visible

            float Z = 0.f;
#pragma unroll
            for (int k = 0; k < 10; k++) Z += s_e[b * 11 + k];
            float c = __fdividef(e, Z);
            unsigned long long cp = pack2(c, c);
#pragma unroll
            for (int j = 0; j < 8; j++) sacc[j] = ffma2(cp, t2[j], sacc[j]);
        } else {
            // c uniform = 1/10: accumulate raw, scale at the end
#pragma unroll
            for (int j = 0; j < 8; j++) sacc[j] = fadd2(sacc[j], t2[j]);
            if (il + 1 < CHUNK) *(float2*)&s_w[(1 - buf) * 1280 + tid * 2] = wpf;
            __syncthreads();   // protect s_w[1-buf] for next il
        }
    }

    // Deterministic per-block partials (layout = output layout b*160+n*16+d)
    float4* po = (float4*)(g_part + (size_t)blockIdx.x * PART_STRIDE + b * ND_ + n * D_);
#pragma unroll
    for (int q = 0; q < 4; q++) {
        float2 f0 = unpack2(sacc[2 * q]);
        float2 f1 = unpack2(sacc[2 * q + 1]);
        if (PASS == 0) { f0.x *= 0.1f; f0.y *= 0.1f; f1.x *= 0.1f; f1.y *= 0.1f; }
        po[q] = make_float4(f0.x, f0.y, f1.x, f1.y);
    }
}

// Two-level 128-way reduction + squash. Grid 320 x 256.
// Block: 8 slices x 32 outputs; slice sums 16 partials (coalesced), smem combine.
// Fixed summation order -> deterministic.
template <bool FINAL>
__global__ __launch_bounds__(256) void k_finish(float* __restrict__ dout) {
    __shared__ float red[8][32];
    int tid = threadIdx.x;
    int s = tid >> 5;
    int ol = tid & 31;
    int o = blockIdx.x * 32 + ol;

    const float* p = g_part + (size_t)(s * 16) * PART_STRIDE + o;
    float a0 = 0.f, a1 = 0.f, a2 = 0.f, a3 = 0.f;
#pragma unroll
    for (int k = 0; k < 16; k += 4) {
        a0 += p[(size_t)(k + 0) * PART_STRIDE];
        a1 += p[(size_t)(k + 1) * PART_STRIDE];
        a2 += p[(size_t)(k + 2) * PART_STRIDE];
        a3 += p[(size_t)(k + 3) * PART_STRIDE];
    }
    red[s][ol] = (a0 + a1) + (a2 + a3);
    __syncthreads();

    if (s == 0) {
        float t0 = red[0][ol] + red[1][ol];
        float t1 = red[2][ol] + red[3][ol];
        float t2 = red[4][ol] + red[5][ol];
        float t3 = red[6][ol] + red[7][ol];
        float sv = (t0 + t1) + (t2 + t3);
        float sq = sv * sv;
        float scale = sq / ((1.f + sq) * sqrtf(sq + 1e-7f));
        float v = scale * sv;
        if (FINAL) dout[o] = v;
        else       g_v[o] = v;
    }
}

extern "C" void kernel_launch(void* const* d_in, const int* in_sizes, int n_in,
                              void* d_out, int out_size) {
    const float* X = (const float*)d_in[0];
    const float* W = (const float*)d_in[1];
    if (n_in >= 2 && in_sizes[0] != B_ * I_ * P_) {
        const float* tmp = X; X = W; W = tmp;
    }

    static int attr_done = 0;
    if (!attr_done) {
        cudaFuncSetAttribute(k_pass<0>, cudaFuncAttributeMaxDynamicSharedMemorySize, SMEM_BYTES);
        cudaFuncSetAttribute(k_pass<1>, cudaFuncAttributeMaxDynamicSharedMemorySize, SMEM_BYTES);
        cudaFuncSetAttribute(k_pass<2>, cudaFuncAttributeMaxDynamicSharedMemorySize, SMEM_BYTES);
        attr_done = 1;
    }

    k_pass<0><<<NBLK, THREADS, SMEM_BYTES>>>(X, W);
    k_finish<false><<<320, 256>>>(nullptr);
    k_pass<1><<<NBLK, THREADS, SMEM_BYTES>>>(X, W);
    k_finish<false><<<320, 256>>>(nullptr);
    k_pass<2><<<NBLK, THREADS, SMEM_BYTES>>>(X, W);
    k_finish<true><<<320, 256>>>((float*)d_out);
}

// round 4
// speedup vs baseline: 1.4675x; 1.0486x over previous
#include <cuda_runtime.h>

// DigitCaps dynamic routing, GB300 sm_103a — full fp32, recompute-fused, R4.
// B=64, I=4096, Din=8, N=10, D=16, 3 routing iterations.
//
// R4 vs R3 (131.8us):
//  - k_pass software-pipelined: ONE __syncthreads per i (was 2), softmax(il)
//    and FMA-recompute(il+1) in the same basic block so they interleave
//  - per-thread softmax with no max-subtraction (logits bounded), no second
//    smem exchange; exps ride the idle MUFU pipe under the FMA work
//  - grid 148 (28/27 i per block) = exactly one wave (was 128/148 SMs)
//  - triple-buffered s_a and s_w so one barrier per il is sufficient
//  - k_finish: 160 blocks x 256, 4 slices x 37 partials, MLP-37 loads

#define B_ 64
#define I_ 4096
#define P_ 8
#define N_ 10
#define D_ 16
#define ND_ 160
#define NBLK 148
#define THREADS 640
#define OUT_ (B_ * ND_)          // 10240

// dynamic smem (floats)
#define SX_SZ (224 * 65)         // x staged [r=il*8+p][b], stride 65 (conflict-free)
#define SW_SZ (3 * 1280)         // triple-buffered W[i][n][p][d]
#define SA_SZ (3 * 704)          // triple-buffered logits, stride 11 per b
#define SMEM_BYTES ((SX_SZ + SW_SZ + SA_SZ) * 4)

__device__ float g_part[(size_t)NBLK * OUT_];   // per-block partials, 6.1MB
__device__ float g_blog[(size_t)I_ * THREADS];  // logits [i][n*64+b], 10.5MB
__device__ float g_v[OUT_];                     // squashed v

typedef unsigned long long ull;

static __device__ __forceinline__ ull pack2(float a, float b) {
    ull r; asm("mov.b64 %0, {%1,%2};" : "=l"(r) : "f"(a), "f"(b)); return r;
}
static __device__ __forceinline__ float2 unpack2(ull v) {
    float2 r; asm("mov.b64 {%0,%1}, %2;" : "=f"(r.x), "=f"(r.y) : "l"(v)); return r;
}
static __device__ __forceinline__ ull ffma2(ull a, ull b, ull c) {
    ull d; asm("fma.rn.f32x2 %0, %1, %2, %3;" : "=l"(d) : "l"(a), "l"(b), "l"(c)); return d;
}
static __device__ __forceinline__ ull fadd2(ull a, ull b) {
    ull d; asm("add.rn.f32x2 %0, %1, %2;" : "=l"(d) : "l"(a), "l"(b)); return d;
}

// t[16] = sum_p x[b, i, p] * W[i, n, p, :]; W from smem buffer, x from s_x rows.
static __device__ __forceinline__ void compute_t(ull t2[8], const float* __restrict__ wbase,
                                                 const float* __restrict__ s_x, int il, int b) {
#pragma unroll
    for (int j = 0; j < 8; j++) t2[j] = 0ULL;
#pragma unroll
    for (int p = 0; p < P_; p++) {
        float xv = s_x[(il * 8 + p) * 65 + b];                 // lane-stride 1: conflict-free
        ull xp = pack2(xv, xv);
        const ulonglong2* wv = (const ulonglong2*)(wbase + p * D_);  // warp-uniform bcast
#pragma unroll
        for (int q = 0; q < 4; q++) {
            ulonglong2 w = wv[q];
            t2[2 * q]     = ffma2(xp, w.x, t2[2 * q]);
            t2[2 * q + 1] = ffma2(xp, w.y, t2[2 * q + 1]);
        }
    }
}

template <int PASS>
__global__ __launch_bounds__(THREADS, 1) void k_pass(const float* __restrict__ X,
                                                     const float* __restrict__ W) {
    extern __shared__ float smem[];
    float* s_x = smem;
    float* s_w = smem + SX_SZ;
    float* s_a = s_w + SW_SZ;

    int tid = threadIdx.x;
    int n = tid >> 6;         // warp-uniform
    int b = tid & 63;
    int blk = blockIdx.x;
    int i0, ni;
    if (blk < 100) { i0 = blk * 28;              ni = 28; }
    else           { i0 = 2800 + (blk - 100) * 27; ni = 27; }

    // ---- stage x: ni*8 floats per batch, coalesced reads, conflict-free writes
    if (ni == 28) {
        for (int idx = tid; idx < 224 * 64; idx += THREADS) {
            int bb = idx / 224; int r = idx - bb * 224;
            s_x[r * 65 + bb] = X[(size_t)bb * (I_ * P_) + i0 * P_ + r];
        }
    } else {
        for (int idx = tid; idx < 216 * 64; idx += THREADS) {
            int bb = idx / 216; int r = idx - bb * 216;
            s_x[r * 65 + bb] = X[(size_t)bb * (I_ * P_) + i0 * P_ + r];
        }
    }
    // ---- stage W(0), W(1)
    {
        float2 w0 = *(const float2*)(W + (size_t)i0 * 1280 + tid * 2);
        *(float2*)(s_w + tid * 2) = w0;
        float2 w1 = *(const float2*)(W + (size_t)(i0 + 1) * 1280 + tid * 2);
        *(float2*)(s_w + 1280 + tid * 2) = w1;
    }
    // ---- v in registers
    ull v2[8];
    if (PASS > 0) {
        const float4* vp = (const float4*)(g_v + b * ND_ + n * D_);
#pragma unroll
        for (int j = 0; j < 4; j++) {
            float4 f = vp[j];
            v2[2 * j] = pack2(f.x, f.y);
            v2[2 * j + 1] = pack2(f.z, f.w);
        }
    }
    __syncthreads();

    // ---- prologue: t(0), agreement(0)
    ull t2[8];
    compute_t(t2, s_w + n * 128, s_x, 0, b);
    if (PASS > 0) {
        ull aa = 0ULL;
#pragma unroll
        for (int j = 0; j < 8; j++) aa = ffma2(t2[j], v2[j], aa);
        float2 af = unpack2(aa);
        float bn = af.x + af.y;
        if (PASS == 2) bn += g_blog[(size_t)i0 * THREADS + tid];
        s_a[b * 11 + n] = bn;
        g_blog[(size_t)i0 * THREADS + tid] = bn;
        __syncthreads();
    }

    ull sacc[8];
#pragma unroll
    for (int j = 0; j < 8; j++) sacc[j] = 0ULL;

    int m0 = 0, m1 = 1, m2 = 2;   // il%3, (il+1)%3, (il+2)%3
    for (int il = 0; il < ni - 1; il++) {
        // prefetches
        float2 wpf;
        bool w_ok = (il + 2 < ni);
        if (w_ok) wpf = *(const float2*)(W + (size_t)(i0 + il + 2) * 1280 + tid * 2);
        float gpf = 0.f;
        if (PASS == 2) gpf = g_blog[(size_t)(i0 + il + 1) * THREADS + tid];

        // softmax(il): per-thread, no max-subtraction (logits bounded), MUFU pipe
        if (PASS > 0) {
            const float* sa = s_a + m0 * 704 + b * 11;
            float Z = 0.f, eo = 0.f;
#pragma unroll
            for (int k = 0; k < 10; k++) {
                float e = __expf(sa[k]);
                Z += e;
                if (k == n) eo = e;
            }
            float c = __fdividef(eo, Z);
            ull cp = pack2(c, c);
#pragma unroll
            for (int j = 0; j < 8; j++) sacc[j] = ffma2(cp, t2[j], sacc[j]);
        } else {
#pragma unroll
            for (int j = 0; j < 8; j++) sacc[j] = fadd2(sacc[j], t2[j]);
        }

        // recompute t(il+1) — independent of softmax; interleaves on the FMA pipe
        compute_t(t2, s_w + m1 * 1280 + n * 128, s_x, il + 1, b);

        if (PASS > 0) {
            ull aa = 0ULL;
#pragma unroll
            for (int j = 0; j < 8; j++) aa = ffma2(t2[j], v2[j], aa);
            float2 af = unpack2(aa);
            float bn = af.x + af.y + (PASS == 2 ? gpf : 0.f);
            s_a[m1 * 704 + b * 11 + n] = bn;
            g_blog[(size_t)(i0 + il + 1) * THREADS + tid] = bn;
        }
        if (w_ok) *(float2*)(s_w + m2 * 1280 + tid * 2) = wpf;

        __syncthreads();
        int tmp = m0; m0 = m1; m1 = m2; m2 = tmp;
    }

    // epilogue: consume t(ni-1)
    if (PASS > 0) {
        const float* sa = s_a + m0 * 704 + b * 11;
        float Z = 0.f, eo = 0.f;
#pragma unroll
        for (int k = 0; k < 10; k++) {
            float e = __expf(sa[k]);
            Z += e;
            if (k == n) eo = e;
        }
        float c = __fdividef(eo, Z);
        ull cp = pack2(c, c);
#pragma unroll
        for (int j = 0; j < 8; j++) sacc[j] = ffma2(cp, t2[j], sacc[j]);
    } else {
#pragma unroll
        for (int j = 0; j < 8; j++) sacc[j] = fadd2(sacc[j], t2[j]);
    }

    // per-block partials (deterministic; layout = output layout b*160+n*16+d)
    float4* po = (float4*)(g_part + (size_t)blk * OUT_ + b * ND_ + n * D_);
#pragma unroll
    for (int q = 0; q < 4; q++) {
        float2 f0 = unpack2(sacc[2 * q]);
        float2 f1 = unpack2(sacc[2 * q + 1]);
        if (PASS == 0) { f0.x *= 0.1f; f0.y *= 0.1f; f1.x *= 0.1f; f1.y *= 0.1f; }
        po[q] = make_float4(f0.x, f0.y, f1.x, f1.y);
    }
}

// 148-way reduction + squash. Grid 160 x 256: 4 slices x 37 partials, 64 outputs
// per block, coalesced MLP-37 loads, fixed order (deterministic).
template <bool FINAL>
__global__ __launch_bounds__(256) void k_finish(float* __restrict__ dout) {
    __shared__ float red[4][64];
    int tid = threadIdx.x;
    int s = tid >> 6;
    int ol = tid & 63;
    int o = blockIdx.x * 64 + ol;

    const float* p = g_part + (size_t)(s * 37) * OUT_ + o;
    float a0 = 0.f, a1 = 0.f, a2 = 0.f, a3 = 0.f;
#pragma unroll
    for (int k = 0; k < 36; k += 4) {
        a0 += p[(size_t)(k + 0) * OUT_];
        a1 += p[(size_t)(k + 1) * OUT_];
        a2 += p[(size_t)(k + 2) * OUT_];
        a3 += p[(size_t)(k + 3) * OUT_];
    }
    red[s][ol] = ((a0 + a1) + (a2 + a3)) + p[(size_t)36 * OUT_];
    __syncthreads();

    if (s == 0) {
        float sv = (red[0][ol] + red[1][ol]) + (red[2][ol] + red[3][ol]);
        float sq = sv * sv;
        float scale = sq / ((1.f + sq) * sqrtf(sq + 1e-7f));
        float v = scale * sv;
        if (FINAL) dout[o] = v;
        else       g_v[o] = v;
    }
}

extern "C" void kernel_launch(void* const* d_in, const int* in_sizes, int n_in,
                              void* d_out, int out_size) {
    const float* X = (const float*)d_in[0];
    const float* W = (const float*)d_in[1];
    if (n_in >= 2 && in_sizes[0] != B_ * I_ * P_) {
        const float* tmp = X; X = W; W = tmp;
    }

    cudaFuncSetAttribute(k_pass<0>, cudaFuncAttributeMaxDynamicSharedMemorySize, SMEM_BYTES);
    cudaFuncSetAttribute(k_pass<1>, cudaFuncAttributeMaxDynamicSharedMemorySize, SMEM_BYTES);
    cudaFuncSetAttribute(k_pass<2>, cudaFuncAttributeMaxDynamicSharedMemorySize, SMEM_BYTES);

    k_pass<0><<<NBLK, THREADS, SMEM_BYTES>>>(X, W);
    k_finish<false><<<160, 256>>>(nullptr);
    k_pass<1><<<NBLK, THREADS, SMEM_BYTES>>>(X, W);
    k_finish<false><<<160, 256>>>(nullptr);
    k_pass<2><<<NBLK, THREADS, SMEM_BYTES>>>(X, W);
    k_finish<true><<<160, 256>>>((float*)d_out);
}